// round 17
// baseline (speedup 1.0000x reference)
#include <cuda_runtime.h>
#include <cuda_bf16.h>

// CopyMechanism (pointer-generator): gate + vocab scale + scatter.
// B=16, T=128, H=512, V=32000, S=400.
//
// R10: single fused kernel, symmetric partial-gate exchange.
//  - Each tile CTA (4 per row) computes a QUARTER of the gate dot product and
//    publishes the partial (single word = data+flag, NaN-bits sentinel).
//  - Each CTA then spins for the other 3 partials (skew-only wait, ~L2 RT),
//    sums in fixed order (deterministic), sigmoid.
//  - Deadlock-free: in-order bid issue + partials published at CTA start.
//  - Streaming scale + range-filtered scatter identical to proven 82us K2.
//  - memset node poisons the 32 KB partial scratch each launch.
//
// Inputs (metadata order):
//  0 context_vecs [B,T,H] f32,  1 hidden [B,T,H] f32,  2 trg_embs [B,T,H] f32
//  3 vocab_dists [B,T,V] f32,   4 attn_dists [B,T,S] f32, 5 src_ids [B,T,S] i32
//  6 pad_id (unused), 7 w_h [1,H], 8 w_s [1,H], 9 w_x_w [1,H], 10 w_x_b [1]
// output: [B,T,V] f32

#define HDIM 512
#define VDIM 32000
#define SDIM 400
#define NROWS 2048
#define NTHREADS 256
#define NWARPS (NTHREADS / 32)
#define TILES_PER_ROW 4
#define TILE_ELEMS (VDIM / TILES_PER_ROW)   // 8000 floats
#define TILE4 (TILE_ELEMS / 4)              // 2000 float4
#define QH2 (HDIM / TILES_PER_ROW / 2)      // 64 float2 per tensor per quarter

#define SENTINEL 0xFFFFFFFFu   // NaN bit pattern; finite dot never produces it

__device__ unsigned int g_part[NROWS * TILES_PER_ROW];

__global__ __launch_bounds__(NTHREADS)
void copy_mechanism_kernel(
    const float* __restrict__ ctx,
    const float* __restrict__ hid,
    const float* __restrict__ trg,
    const float* __restrict__ vocab,
    const float* __restrict__ attn,
    const int*   __restrict__ src_ids,
    const float* __restrict__ w_h,
    const float* __restrict__ w_s,
    const float* __restrict__ w_x,
    const float* __restrict__ w_b,
    float* __restrict__ out)
{
    const int row  = blockIdx.x >> 2;       // 0 .. NROWS-1
    const int tile = blockIdx.x & 3;        // quarter of the row
    const int tid  = threadIdx.x;
    const int lane = tid & 31;
    const int warp = tid >> 5;

    __shared__ float s_red[NWARPS];
    __shared__ float s_pgen;

    // ---- Phase 1a: quarter gate partial (threads 0..191 active) ----
    // Quarter covers H-elements [tile*128, tile*128+128) = float2 [tile*64 .. +64).
    // Thread groups of 64 handle ctx/w_h, hid/w_s, trg/w_x respectively.
    {
        float acc = 0.0f;
        if (tid < 3 * QH2) {
            const int grp = tid / QH2;           // 0,1,2 -> which tensor
            const int off = tile * QH2 + (tid % QH2);   // float2 index in row
            const float2* ten;
            const float2* wgt;
            if (grp == 0) {
                ten = reinterpret_cast<const float2*>(ctx + (size_t)row * HDIM);
                wgt = reinterpret_cast<const float2*>(w_h);
            } else if (grp == 1) {
                ten = reinterpret_cast<const float2*>(hid + (size_t)row * HDIM);
                wgt = reinterpret_cast<const float2*>(w_s);
            } else {
                ten = reinterpret_cast<const float2*>(trg + (size_t)row * HDIM);
                wgt = reinterpret_cast<const float2*>(w_x);
            }
            float2 v = ten[off];
            float2 w = wgt[off];
            acc = v.x * w.x + v.y * w.y;
        }
        #pragma unroll
        for (int o = 16; o > 0; o >>= 1)
            acc += __shfl_down_sync(0xFFFFFFFFu, acc, o);
        if (lane == 0) s_red[warp] = acc;
    }
    __syncthreads();

    // ---- Phase 1b: publish partial, spin for peers, sigmoid ----
    if (tid == 0) {
        float part = 0.0f;
        #pragma unroll
        for (int w = 0; w < NWARPS; w++) part += s_red[w];
        // Publish own partial (value doubles as readiness flag).
        *((volatile unsigned int*)&g_part[row * TILES_PER_ROW + tile]) =
            __float_as_uint(part);

        // Gather all 4 partials in fixed order (deterministic sum).
        float logit = w_b[0];
        #pragma unroll
        for (int t = 0; t < TILES_PER_ROW; t++) {
            volatile unsigned int* p =
                (volatile unsigned int*)&g_part[row * TILES_PER_ROW + t];
            unsigned int v = *p;
            while (v == SENTINEL) { __nanosleep(32); v = *p; }
            logit += __uint_as_float(v);
        }
        s_pgen = 1.0f / (1.0f + __expf(-logit));
    }
    __syncthreads();

    const float p_gen     = s_pgen;
    const float one_minus = 1.0f - p_gen;

    // ---- Phase 2: streaming scale over this quarter (proven K2 body) ----
    {
        const float4* v4 = reinterpret_cast<const float4*>(vocab + (size_t)row * VDIM)
                         + tile * TILE4;
        float4* o4 = reinterpret_cast<float4*>(out + (size_t)row * VDIM)
                   + tile * TILE4;
        #pragma unroll 4
        for (int i = tid; i < TILE4; i += NTHREADS) {
            float4 v = v4[i];
            v.x *= p_gen; v.y *= p_gen; v.z *= p_gen; v.w *= p_gen;
            o4[i] = v;
        }
    }

    __syncthreads();   // tile fully written before scatter RMW into it

    // ---- Phase 3: range-filtered scatter-add into THIS tile only ----
    {
        const int lo = tile * TILE_ELEMS;
        const int hi = lo + TILE_ELEMS;
        const float* a   = attn + (size_t)row * SDIM;
        const int*   ids = src_ids + (size_t)row * SDIM;
        float* orow = out + (size_t)row * VDIM;
        for (int j = tid; j < SDIM; j += NTHREADS) {
            int id = ids[j];
            if (id >= lo && id < hi)
                atomicAdd(&orow[id], one_minus * a[j]);
        }
    }
}

extern "C" void kernel_launch(void* const* d_in, const int* in_sizes, int n_in,
                              void* d_out, int out_size) {
    const float* ctx   = (const float*)d_in[0];
    const float* hid   = (const float*)d_in[1];
    const float* trg   = (const float*)d_in[2];
    const float* vocab = (const float*)d_in[3];
    const float* attn  = (const float*)d_in[4];
    const int*   sid   = (const int*)d_in[5];
    const float* w_h   = (const float*)d_in[7];
    const float* w_s   = (const float*)d_in[8];
    const float* w_x   = (const float*)d_in[9];
    const float* w_b   = (const float*)d_in[10];
    float* out = (float*)d_out;

    // Poison partial scratch each launch (graph-capturable, no alloc).
    void* part_ptr = nullptr;
    cudaGetSymbolAddress(&part_ptr, g_part);
    cudaMemsetAsync(part_ptr, 0xFF,
                    NROWS * TILES_PER_ROW * sizeof(unsigned int), 0);

    copy_mechanism_kernel<<<NROWS * TILES_PER_ROW, NTHREADS>>>(
        ctx, hid, trg, vocab, attn, sid, w_h, w_s, w_x, w_b, out);
}